// round 9
// baseline (speedup 1.0000x reference)
#include <cuda_runtime.h>
#include <cuda_fp16.h>
#include <math.h>

#define NN   100000
#define EE   1600000
#define C    32
#define KK   5
#define L1   (KK*C)          // 160
#define EPSV 1e-15f
#define BNE  1e-5f

#define NB   48              // nodes per conv block
#define ZROW1 196            // z row stride (words) conv1: 160 z + 32 zs + pad
#define ZROW2 164            // conv2: 160 z + pad

// ------------------------- device scratch (no allocs) -------------------------
__device__ float  g_y1 [(size_t)NN*C];
__device__ float  g_ys [(size_t)NN*C];
__device__ float  g_y2 [(size_t)NN*C];
__device__ float  g_h1 [(size_t)NN*C];
__device__ int    g_cnt[NN];
__device__ int    g_ptr[NN+1];
__device__ int    g_pos[NN];
__device__ int    g_bsum[128];
__device__ float  g_stat[8*C];     // [sum_y1, sq_y1, sum_ys, sq_ys, sum_y2, sq_y2, -, -]
__device__ float  g_bns[6*C];      // [sc1, sh1, scs, shs, sc2, sh2]
__device__ float4 g_gpar[22];      // 11 gaussian comps: {mu0,mu1,mu2,_},{i0,i1,i2,_}
// per-CSR-edge compressed meta, interleaved 32B (full-sector scatter writes):
//   g_m[2p]   = {src:int, half2(w1_0,w1_1), half2(w1_2,w1_3), half2(w1_4, ws)}
//   g_m[2p+1] = {src:int, half2(w2_0,w2_1), half2(w2_2,w2_3), half2(w2_4, 0)}
__device__ uint4  g_m[(size_t)2*EE];

__device__ __forceinline__ float2 h2f(unsigned int u) {
    __half2 h = *reinterpret_cast<__half2*>(&u);
    return __half22float2(h);
}
__device__ __forceinline__ unsigned int f2h(float a, float b) {
    __half2 h = __floats2half2_rn(a, b);
    return *reinterpret_cast<unsigned int*>(&h);
}

// ------------------- zero scratch + gaussian param prep ----------------------
__global__ void k_zg(const float* __restrict__ mu1, const float* __restrict__ sg1,
                     const float* __restrict__ mu2, const float* __restrict__ sg2,
                     const float* __restrict__ mus, const float* __restrict__ sgs) {
    int i = blockIdx.x * 256 + threadIdx.x;
    if (i < NN)   g_cnt[i] = 0;
    if (i < 8*C)  g_stat[i] = 0.f;
    if (i < 11) {
        const float* mu; const float* sg; int k;
        if (i < 5)       { mu = mu1; sg = sg1; k = i; }
        else if (i < 10) { mu = mu2; sg = sg2; k = i - 5; }
        else             { mu = mus; sg = sgs; k = 0; }
        float m0 = mu[3*k], m1 = mu[3*k+1], m2 = mu[3*k+2];
        float s0 = sg[3*k], s1 = sg[3*k+1], s2 = sg[3*k+2];
        g_gpar[2*i]     = make_float4(m0, m1, m2, 0.f);
        g_gpar[2*i + 1] = make_float4(1.f/(EPSV + s0*s0), 1.f/(EPSV + s1*s1), 1.f/(EPSV + s2*s2), 0.f);
    }
}

// ------------------------------ CSR build ------------------------------------
__global__ void k_count(const int* __restrict__ ei) {
    int e = blockIdx.x * 256 + threadIdx.x;
    if (e < EE) atomicAdd(&g_cnt[ei[EE + e]], 1);
}

__global__ void k_scan1() {
    __shared__ int sd[1024];
    int tid = threadIdx.x;
    int i = blockIdx.x * 1024 + tid;
    int v = (i < NN) ? g_cnt[i] : 0;
    sd[tid] = v; __syncthreads();
    for (int off = 1; off < 1024; off <<= 1) {
        int t = (tid >= off) ? sd[tid - off] : 0;
        __syncthreads();
        sd[tid] += t; __syncthreads();
    }
    if (i < NN) g_ptr[i] = sd[tid] - v;           // block-local exclusive
    if (tid == 1023) g_bsum[blockIdx.x] = sd[1023];
}

__global__ void k_scan2(int nb) {
    __shared__ int ws[4];
    int t = threadIdx.x;                  // 128 threads
    int lane = t & 31, w = t >> 5;
    int orig = (t < nb) ? g_bsum[t] : 0;
    int v = orig;
    #pragma unroll
    for (int o = 1; o < 32; o <<= 1) {
        int u = __shfl_up_sync(0xffffffffu, v, o);
        if (lane >= o) v += u;
    }
    if (lane == 31) ws[w] = v;
    __syncthreads();
    int add = 0;
    #pragma unroll
    for (int i = 0; i < 4; i++) if (i < w) add += ws[i];
    v += add;
    if (t < nb) g_bsum[t] = v - orig;     // exclusive
}

__global__ void k_scan3() {
    int i = blockIdx.x * 256 + threadIdx.x;
    if (i < NN) {
        int p = g_ptr[i] + g_bsum[i >> 10];
        g_ptr[i] = p; g_pos[i] = p;
    }
    if (i == 0) g_ptr[NN] = EE;
}

// ---- fill: scatter edges into CSR; gaussian weights from hoisted params -----
__global__ void k_fill(const int* __restrict__ ei, const float* __restrict__ attr) {
    int e = blockIdx.x * 256 + threadIdx.x;
    if (e >= EE) return;
    int s = ei[e], d = ei[EE + e];
    float a0 = attr[3*e], a1 = attr[3*e + 1], a2 = attr[3*e + 2];
    float w[11];
    #pragma unroll
    for (int t = 0; t < 11; t++) {
        float4 mu = __ldg(&g_gpar[2*t]);
        float4 iv = __ldg(&g_gpar[2*t + 1]);
        float d0 = a0 - mu.x, d1 = a1 - mu.y, d2 = a2 - mu.z;
        w[t] = __expf(-0.5f * (d0*d0*iv.x + d1*d1*iv.y + d2*d2*iv.z));
    }
    int p = atomicAdd(&g_pos[d], 1);
    uint4 v1, v2;
    v1.x = (unsigned int)s;  v1.y = f2h(w[0], w[1]); v1.z = f2h(w[2], w[3]); v1.w = f2h(w[4], w[10]);
    v2.x = (unsigned int)s;  v2.y = f2h(w[5], w[6]); v2.z = f2h(w[7], w[8]); v2.w = f2h(w[9], 0.f);
    g_m[2*(size_t)p]     = v1;            // full 32B sector per edge
    g_m[2*(size_t)p + 1] = v2;
}

// ========== fused conv1: edge gather (K=5 + shortcut) -> smem z -> GEMM ======
// block = 192 threads = 6 warps; 48 nodes/block (8 per warp, sequential).
// dynamic smem: zsh[48][196]; total static+dynamic ~73.5KB (attribute raised).
__global__ void k_conv1(const float* __restrict__ x,
                        const float* __restrict__ g1, const float* __restrict__ gs,
                        const float* __restrict__ root1, const float* __restrict__ b1,
                        const float* __restrict__ roots, const float* __restrict__ bs) {
    __shared__ float B1[L1][C];      // B1[k*32+i][o] = g1[i][k*32+o]
    __shared__ float Bs[C][C];
    __shared__ float W1[C][C];
    __shared__ float Ws[C][C];
    __shared__ float red[6][4][C];
    extern __shared__ float zsh[];   // [NB][ZROW1]
    int tid = threadIdx.x;
    for (int idx = tid; idx < C*L1; idx += 192) {
        int i = idx / L1, r = idx % L1;
        B1[(r >> 5)*32 + i][r & 31] = g1[idx];
    }
    for (int idx = tid; idx < C*C; idx += 192) {
        Bs[idx >> 5][idx & 31] = gs[idx];
        W1[idx >> 5][idx & 31] = root1[idx];
        Ws[idx >> 5][idx & 31] = roots[idx];
    }
    int w = tid >> 5, lane = tid & 31;
    int n0 = blockIdx.x * NB;
    // ---------- phase A: edge gather, 8 nodes per warp ----------
    for (int t = 0; t < 8; t++) {
        int l = w*8 + t;
        int n = n0 + l;
        if (n < NN) {
            int beg = __ldg(&g_ptr[n]), end = __ldg(&g_ptr[n + 1]);
            float a0 = 0.f, a1 = 0.f, a2 = 0.f, a3 = 0.f, a4 = 0.f, aS = 0.f;
            int j = beg;
            for (; j + 8 <= end; j += 8) {
                uint4 m[8];
                #pragma unroll
                for (int u = 0; u < 8; u++) m[u] = __ldg(&g_m[2*(size_t)(j + u)]);
                float xv[8];
                #pragma unroll
                for (int u = 0; u < 8; u++)
                    xv[u] = __ldg(x + (size_t)(int)m[u].x * C + lane);
                #pragma unroll
                for (int u = 0; u < 8; u++) {
                    float2 w01 = h2f(m[u].y), w23 = h2f(m[u].z), w4s = h2f(m[u].w);
                    a0 += w01.x * xv[u]; a1 += w01.y * xv[u];
                    a2 += w23.x * xv[u]; a3 += w23.y * xv[u];
                    a4 += w4s.x * xv[u]; aS += w4s.y * xv[u];
                }
            }
            for (; j < end; j++) {
                uint4 m = __ldg(&g_m[2*(size_t)j]);
                float xv = __ldg(x + (size_t)(int)m.x * C + lane);
                float2 w01 = h2f(m.y), w23 = h2f(m.z), w4s = h2f(m.w);
                a0 += w01.x * xv; a1 += w01.y * xv;
                a2 += w23.x * xv; a3 += w23.y * xv;
                a4 += w4s.x * xv; aS += w4s.y * xv;
            }
            float inv = 1.f / fmaxf((float)(end - beg), 1.f);
            float* zr = zsh + (size_t)l * ZROW1;
            zr[lane]       = a0 * inv;
            zr[32 + lane]  = a1 * inv;
            zr[64 + lane]  = a2 * inv;
            zr[96 + lane]  = a3 * inv;
            zr[128 + lane] = a4 * inv;
            zr[160 + lane] = aS * inv;
        }
    }
    __syncthreads();
    // ---------- phase B: y1 = z1@B1 + x@W1 + b1 ; ys = zs@Bs + x@Ws + bs -----
    int l = tid >> 2;                  // local node 0..47
    int n = n0 + l;
    int q = (tid & 3) * 8;
    bool valid = (n < NN);
    float acc[8]  = {0,0,0,0,0,0,0,0};
    float accs[8] = {0,0,0,0,0,0,0,0};
    if (valid) {
        {
            float4 ba = __ldg((const float4*)(b1 + q));
            float4 bb = __ldg((const float4*)(b1 + q + 4));
            acc[0]=ba.x; acc[1]=ba.y; acc[2]=ba.z; acc[3]=ba.w;
            acc[4]=bb.x; acc[5]=bb.y; acc[6]=bb.z; acc[7]=bb.w;
            float4 ca = __ldg((const float4*)(bs + q));
            float4 cb = __ldg((const float4*)(bs + q + 4));
            accs[0]=ca.x; accs[1]=ca.y; accs[2]=ca.z; accs[3]=ca.w;
            accs[4]=cb.x; accs[5]=cb.y; accs[6]=cb.z; accs[7]=cb.w;
        }
        const float* zr = zsh + (size_t)l * ZROW1;
        #pragma unroll
        for (int j = 0; j < L1; j += 4) {
            float4 zv = *(const float4*)(zr + j);
            #pragma unroll
            for (int jj = 0; jj < 4; jj++) {
                float s = (&zv.x)[jj];
                float4 wa = *(const float4*)&B1[j + jj][q];
                float4 wb = *(const float4*)&B1[j + jj][q + 4];
                acc[0] += s*wa.x; acc[1] += s*wa.y; acc[2] += s*wa.z; acc[3] += s*wa.w;
                acc[4] += s*wb.x; acc[5] += s*wb.y; acc[6] += s*wb.z; acc[7] += s*wb.w;
            }
        }
        #pragma unroll
        for (int j = 0; j < C; j += 4) {
            float4 zv = *(const float4*)(zr + 160 + j);
            #pragma unroll
            for (int jj = 0; jj < 4; jj++) {
                float s = (&zv.x)[jj];
                float4 wa = *(const float4*)&Bs[j + jj][q];
                float4 wb = *(const float4*)&Bs[j + jj][q + 4];
                accs[0] += s*wa.x; accs[1] += s*wa.y; accs[2] += s*wa.z; accs[3] += s*wa.w;
                accs[4] += s*wb.x; accs[5] += s*wb.y; accs[6] += s*wb.z; accs[7] += s*wb.w;
            }
        }
        const float* xr = x + (size_t)n * C;
        #pragma unroll
        for (int j = 0; j < C; j += 4) {
            float4 xv = __ldg((const float4*)(xr + j));
            #pragma unroll
            for (int jj = 0; jj < 4; jj++) {
                float s = (&xv.x)[jj];
                float4 wa = *(const float4*)&W1[j + jj][q];
                float4 wb = *(const float4*)&W1[j + jj][q + 4];
                acc[0] += s*wa.x; acc[1] += s*wa.y; acc[2] += s*wa.z; acc[3] += s*wa.w;
                acc[4] += s*wb.x; acc[5] += s*wb.y; acc[6] += s*wb.z; acc[7] += s*wb.w;
                float4 va = *(const float4*)&Ws[j + jj][q];
                float4 vb = *(const float4*)&Ws[j + jj][q + 4];
                accs[0] += s*va.x; accs[1] += s*va.y; accs[2] += s*va.z; accs[3] += s*va.w;
                accs[4] += s*vb.x; accs[5] += s*vb.y; accs[6] += s*vb.z; accs[7] += s*vb.w;
            }
        }
        size_t b = (size_t)n * C + q;
        *(float4*)(g_y1 + b)     = make_float4(acc[0], acc[1], acc[2], acc[3]);
        *(float4*)(g_y1 + b + 4) = make_float4(acc[4], acc[5], acc[6], acc[7]);
        *(float4*)(g_ys + b)     = make_float4(accs[0], accs[1], accs[2], accs[3]);
        *(float4*)(g_ys + b + 4) = make_float4(accs[4], accs[5], accs[6], accs[7]);
    }
    // ---- fused BN statistics ----
    float sq[8], sqs[8];
    #pragma unroll
    for (int i = 0; i < 8; i++) { sq[i] = acc[i]*acc[i]; sqs[i] = accs[i]*accs[i]; }
    #pragma unroll
    for (int o = 4; o < 32; o <<= 1) {
        #pragma unroll
        for (int i = 0; i < 8; i++) {
            acc[i]  += __shfl_xor_sync(0xffffffffu, acc[i],  o);
            sq[i]   += __shfl_xor_sync(0xffffffffu, sq[i],   o);
            accs[i] += __shfl_xor_sync(0xffffffffu, accs[i], o);
            sqs[i]  += __shfl_xor_sync(0xffffffffu, sqs[i],  o);
        }
    }
    if (lane < 4) {
        #pragma unroll
        for (int i = 0; i < 8; i++) {
            red[w][0][lane*8 + i] = acc[i];
            red[w][1][lane*8 + i] = sq[i];
            red[w][2][lane*8 + i] = accs[i];
            red[w][3][lane*8 + i] = sqs[i];
        }
    }
    __syncthreads();
    if (tid < 128) {
        float t = 0.f;
        #pragma unroll
        for (int ww = 0; ww < 6; ww++) t += red[ww][tid >> 5][tid & 31];
        atomicAdd(&g_stat[tid], t);
    }
}

__global__ void k_finA(const float* __restrict__ gam1, const float* __restrict__ bet1,
                       const float* __restrict__ gams, const float* __restrict__ bets) {
    int t = threadIdx.x;
    const float invn = 1.f / (float)NN;
    if (t < 32) {
        float m = g_stat[t] * invn;
        float v = g_stat[32 + t] * invn - m*m;
        float sc = gam1[t] * rsqrtf(v + BNE);
        g_bns[t] = sc; g_bns[32 + t] = bet1[t] - m*sc;
    } else if (t < 64) {
        int c = t - 32;
        float m = g_stat[64 + c] * invn;
        float v = g_stat[96 + c] * invn - m*m;
        float sc = gams[c] * rsqrtf(v + BNE);
        g_bns[64 + c] = sc; g_bns[96 + c] = bets[c] - m*sc;
    }
}

// --------------- prepB: h1 = elu(BN1(y1))  (pure elementwise) ----------------
__global__ void k_prepB() {
    int i4 = blockIdx.x * 256 + threadIdx.x;     // group of 4 elements
    if (i4 >= NN*C/4) return;
    int c4 = (i4 & 7) * 4;
    float4 y  = *(const float4*)(g_y1 + (size_t)i4 * 4);
    float4 sc = *(const float4*)(g_bns + c4);
    float4 sh = *(const float4*)(g_bns + 32 + c4);
    float v0 = y.x*sc.x + sh.x, v1 = y.y*sc.y + sh.y;
    float v2 = y.z*sc.z + sh.z, v3 = y.w*sc.w + sh.w;
    float4 h4;
    h4.x = (v0 > 0.f) ? v0 : expm1f(v0);
    h4.y = (v1 > 0.f) ? v1 : expm1f(v1);
    h4.z = (v2 > 0.f) ? v2 : expm1f(v2);
    h4.w = (v3 > 0.f) ? v3 : expm1f(v3);
    *(float4*)(g_h1 + (size_t)i4 * 4) = h4;
}

// ========== fused conv2: edge gather (K=5) -> smem z -> GEMM + stats =========
__global__ void k_conv2(const float* __restrict__ g2, const float* __restrict__ root2,
                        const float* __restrict__ b2) {
    __shared__ float B2[L1][C];
    __shared__ float W2[C][C];
    __shared__ float red[6][2][C];
    extern __shared__ float zsh[];   // [NB][ZROW2]
    int tid = threadIdx.x;
    for (int idx = tid; idx < C*L1; idx += 192) {
        int i = idx / L1, r = idx % L1;
        B2[(r >> 5)*32 + i][r & 31] = g2[idx];
    }
    for (int idx = tid; idx < C*C; idx += 192)
        W2[idx >> 5][idx & 31] = root2[idx];
    int w = tid >> 5, lane = tid & 31;
    int n0 = blockIdx.x * NB;
    // ---------- phase A ----------
    for (int t = 0; t < 8; t++) {
        int l = w*8 + t;
        int n = n0 + l;
        if (n < NN) {
            int beg = __ldg(&g_ptr[n]), end = __ldg(&g_ptr[n + 1]);
            float a0 = 0.f, a1 = 0.f, a2 = 0.f, a3 = 0.f, a4 = 0.f;
            int j = beg;
            for (; j + 8 <= end; j += 8) {
                uint4 m[8];
                #pragma unroll
                for (int u = 0; u < 8; u++) m[u] = __ldg(&g_m[2*(size_t)(j + u) + 1]);
                float hv[8];
                #pragma unroll
                for (int u = 0; u < 8; u++)
                    hv[u] = __ldg(&g_h1[(size_t)(int)m[u].x * C + lane]);
                #pragma unroll
                for (int u = 0; u < 8; u++) {
                    float2 w01 = h2f(m[u].y), w23 = h2f(m[u].z), w4x = h2f(m[u].w);
                    a0 += w01.x * hv[u]; a1 += w01.y * hv[u];
                    a2 += w23.x * hv[u]; a3 += w23.y * hv[u];
                    a4 += w4x.x * hv[u];
                }
            }
            for (; j < end; j++) {
                uint4 m = __ldg(&g_m[2*(size_t)j + 1]);
                float hv = __ldg(&g_h1[(size_t)(int)m.x * C + lane]);
                float2 w01 = h2f(m.y), w23 = h2f(m.z), w4x = h2f(m.w);
                a0 += w01.x * hv; a1 += w01.y * hv;
                a2 += w23.x * hv; a3 += w23.y * hv;
                a4 += w4x.x * hv;
            }
            float inv = 1.f / fmaxf((float)(end - beg), 1.f);
            float* zr = zsh + (size_t)l * ZROW2;
            zr[lane]       = a0 * inv;
            zr[32 + lane]  = a1 * inv;
            zr[64 + lane]  = a2 * inv;
            zr[96 + lane]  = a3 * inv;
            zr[128 + lane] = a4 * inv;
        }
    }
    __syncthreads();
    // ---------- phase B: y2 = z2@B2 + h1@W2 + b2 ----------
    int l = tid >> 2;
    int n = n0 + l;
    int q = (tid & 3) * 8;
    bool valid = (n < NN);
    float acc[8] = {0,0,0,0,0,0,0,0};
    if (valid) {
        {
            float4 ba = __ldg((const float4*)(b2 + q));
            float4 bb = __ldg((const float4*)(b2 + q + 4));
            acc[0]=ba.x; acc[1]=ba.y; acc[2]=ba.z; acc[3]=ba.w;
            acc[4]=bb.x; acc[5]=bb.y; acc[6]=bb.z; acc[7]=bb.w;
        }
        const float* zr = zsh + (size_t)l * ZROW2;
        #pragma unroll
        for (int j = 0; j < L1; j += 4) {
            float4 zv = *(const float4*)(zr + j);
            #pragma unroll
            for (int jj = 0; jj < 4; jj++) {
                float s = (&zv.x)[jj];
                float4 wa = *(const float4*)&B2[j + jj][q];
                float4 wb = *(const float4*)&B2[j + jj][q + 4];
                acc[0] += s*wa.x; acc[1] += s*wa.y; acc[2] += s*wa.z; acc[3] += s*wa.w;
                acc[4] += s*wb.x; acc[5] += s*wb.y; acc[6] += s*wb.z; acc[7] += s*wb.w;
            }
        }
        const float* hr = g_h1 + (size_t)n * C;
        #pragma unroll
        for (int j = 0; j < C; j += 4) {
            float4 hv = __ldg((const float4*)(hr + j));
            #pragma unroll
            for (int jj = 0; jj < 4; jj++) {
                float s = (&hv.x)[jj];
                float4 wa = *(const float4*)&W2[j + jj][q];
                float4 wb = *(const float4*)&W2[j + jj][q + 4];
                acc[0] += s*wa.x; acc[1] += s*wa.y; acc[2] += s*wa.z; acc[3] += s*wa.w;
                acc[4] += s*wb.x; acc[5] += s*wb.y; acc[6] += s*wb.z; acc[7] += s*wb.w;
            }
        }
        size_t b = (size_t)n * C + q;
        *(float4*)(g_y2 + b)     = make_float4(acc[0], acc[1], acc[2], acc[3]);
        *(float4*)(g_y2 + b + 4) = make_float4(acc[4], acc[5], acc[6], acc[7]);
    }
    float sq[8];
    #pragma unroll
    for (int i = 0; i < 8; i++) sq[i] = acc[i]*acc[i];
    #pragma unroll
    for (int o = 4; o < 32; o <<= 1) {
        #pragma unroll
        for (int i = 0; i < 8; i++) {
            acc[i] += __shfl_xor_sync(0xffffffffu, acc[i], o);
            sq[i]  += __shfl_xor_sync(0xffffffffu, sq[i],  o);
        }
    }
    if (lane < 4) {
        #pragma unroll
        for (int i = 0; i < 8; i++) {
            red[w][0][lane*8 + i] = acc[i];
            red[w][1][lane*8 + i] = sq[i];
        }
    }
    __syncthreads();
    if (tid < 64) {
        float t = 0.f;
        #pragma unroll
        for (int ww = 0; ww < 6; ww++) t += red[ww][tid >> 5][tid & 31];
        atomicAdd(&g_stat[128 + tid], t);
    }
}

__global__ void k_finB(const float* __restrict__ gam2, const float* __restrict__ bet2) {
    int t = threadIdx.x;
    if (t < 32) {
        const float invn = 1.f / (float)NN;
        float m = g_stat[128 + t] * invn;
        float v = g_stat[160 + t] * invn - m*m;
        float sc = gam2[t] * rsqrtf(v + BNE);
        g_bns[128 + t] = sc; g_bns[160 + t] = bet2[t] - m*sc;
    }
}

// ------------------- final: out = elu(BN2(y2) + BNs(ys)) ---------------------
__global__ void k_final(float* __restrict__ out) {
    int i = blockIdx.x * 256 + threadIdx.x;
    if (i >= NN*C) return;
    int c = i & 31;
    float v2 = g_y2[i] * g_bns[128 + c] + g_bns[160 + c];
    float vs = g_ys[i] * g_bns[64 + c]  + g_bns[96 + c];
    float h = v2 + vs;
    out[i] = (h > 0.f) ? h : expm1f(h);
}

// ------------------------------------------------------------------------------
extern "C" void kernel_launch(void* const* d_in, const int* in_sizes, int n_in,
                              void* d_out, int out_size) {
    (void)in_sizes; (void)n_in; (void)out_size;
    const float* x     = (const float*)d_in[0];
    const int*   ei    = (const int*)  d_in[1];
    const float* attr  = (const float*)d_in[2];
    const float* g1    = (const float*)d_in[3];
    const float* mu1   = (const float*)d_in[4];
    const float* sg1   = (const float*)d_in[5];
    const float* root1 = (const float*)d_in[6];
    const float* b1    = (const float*)d_in[7];
    const float* gam1  = (const float*)d_in[8];
    const float* bet1  = (const float*)d_in[9];
    const float* g2    = (const float*)d_in[10];
    const float* mu2   = (const float*)d_in[11];
    const float* sg2   = (const float*)d_in[12];
    const float* root2 = (const float*)d_in[13];
    const float* b2    = (const float*)d_in[14];
    const float* gam2  = (const float*)d_in[15];
    const float* bet2  = (const float*)d_in[16];
    const float* gs    = (const float*)d_in[17];
    const float* mus   = (const float*)d_in[18];
    const float* sgs   = (const float*)d_in[19];
    const float* roots = (const float*)d_in[20];
    const float* bs    = (const float*)d_in[21];
    const float* gams  = (const float*)d_in[22];
    const float* bets  = (const float*)d_in[23];
    float* out = (float*)d_out;

    const int nb_scan = (NN + 1023) / 1024;
    const int nb_conv = (NN + NB - 1) / NB;
    const size_t smem1 = (size_t)NB * ZROW1 * sizeof(float);   // 37632 B
    const size_t smem2 = (size_t)NB * ZROW2 * sizeof(float);   // 31488 B

    // raise combined smem limit for the fused conv kernels (static ~35KB + dynamic)
    cudaFuncSetAttribute(k_conv1, cudaFuncAttributeMaxDynamicSharedMemorySize, (int)smem1);
    cudaFuncSetAttribute(k_conv2, cudaFuncAttributeMaxDynamicSharedMemorySize, (int)smem2);

    k_zg   <<<(NN + 255)/256, 256>>>(mu1, sg1, mu2, sg2, mus, sgs);
    k_count<<<(EE + 255)/256, 256>>>(ei);
    k_scan1<<<nb_scan, 1024>>>();
    k_scan2<<<1, 128>>>(nb_scan);
    k_scan3<<<(NN + 255)/256, 256>>>();
    k_fill <<<(EE + 255)/256, 256>>>(ei, attr);
    k_conv1<<<nb_conv, 192, smem1>>>(x, g1, gs, root1, b1, roots, bs);
    k_finA <<<1, 64>>>(gam1, bet1, gams, bets);
    k_prepB<<<(NN*C/4 + 255)/256, 256>>>();
    k_conv2<<<nb_conv, 192, smem2>>>(g2, root2, b2);
    k_finB <<<1, 32>>>(gam2, bet2);
    k_final<<<(NN*C + 255)/256, 256>>>(out);
}

// round 10
// speedup vs baseline: 1.2530x; 1.2530x over previous
#include <cuda_runtime.h>
#include <cuda_fp16.h>
#include <math.h>

#define NN   100000
#define EE   1600000
#define C    32
#define KK   5
#define L1   (KK*C)          // 160
#define EPSV 1e-15f
#define BNE  1e-5f

// ------------------------- device scratch (no allocs) -------------------------
__device__ float  g_z1 [(size_t)NN*L1];
__device__ float  g_zs [(size_t)NN*C];
__device__ float  g_z2 [(size_t)NN*L1];
__device__ float  g_y1 [(size_t)NN*C];
__device__ float  g_ys [(size_t)NN*C];
__device__ float  g_y2 [(size_t)NN*C];
__device__ float  g_h1 [(size_t)NN*C];
__device__ int    g_cnt[NN];
__device__ int    g_ptr[NN+1];
__device__ int    g_pos[NN];
__device__ int    g_bsum[128];
__device__ float  g_stat[8*C];     // [sum_y1, sq_y1, sum_ys, sq_ys, sum_y2, sq_y2, -, -]
__device__ float4 g_gpar[22];      // 11 gaussian comps: {mu0,mu1,mu2,_},{i0,i1,i2,_}
// per-CSR-edge compressed meta, interleaved 32B (full-sector scatter writes):
//   g_m[2p]   = {src:int, half2(w1_0,w1_1), half2(w1_2,w1_3), half2(w1_4, ws)}
//   g_m[2p+1] = {src:int, half2(w2_0,w2_1), half2(w2_2,w2_3), half2(w2_4, 0)}
__device__ uint4  g_m[(size_t)2*EE];

__device__ __forceinline__ float2 h2f(unsigned int u) {
    __half2 h = *reinterpret_cast<__half2*>(&u);
    return __half22float2(h);
}
__device__ __forceinline__ unsigned int f2h(float a, float b) {
    __half2 h = __floats2half2_rn(a, b);
    return *reinterpret_cast<unsigned int*>(&h);
}

// ------------------- zero scratch + gaussian param prep ----------------------
__global__ void k_zg(const float* __restrict__ mu1, const float* __restrict__ sg1,
                     const float* __restrict__ mu2, const float* __restrict__ sg2,
                     const float* __restrict__ mus, const float* __restrict__ sgs) {
    int i = blockIdx.x * 256 + threadIdx.x;
    if (i < NN)   g_cnt[i] = 0;
    if (i < 8*C)  g_stat[i] = 0.f;
    if (i < 11) {
        const float* mu; const float* sg; int k;
        if (i < 5)       { mu = mu1; sg = sg1; k = i; }
        else if (i < 10) { mu = mu2; sg = sg2; k = i - 5; }
        else             { mu = mus; sg = sgs; k = 0; }
        float m0 = mu[3*k], m1 = mu[3*k+1], m2 = mu[3*k+2];
        float s0 = sg[3*k], s1 = sg[3*k+1], s2 = sg[3*k+2];
        g_gpar[2*i]     = make_float4(m0, m1, m2, 0.f);
        g_gpar[2*i + 1] = make_float4(1.f/(EPSV + s0*s0), 1.f/(EPSV + s1*s1), 1.f/(EPSV + s2*s2), 0.f);
    }
}

// ------------------------------ CSR build ------------------------------------
__global__ void k_count(const int* __restrict__ ei) {
    int idx = blockIdx.x * 256 + threadIdx.x;
    if (idx * 4 >= EE) return;
    int4 d = __ldg((const int4*)(ei + EE) + idx);
    atomicAdd(&g_cnt[d.x], 1);
    atomicAdd(&g_cnt[d.y], 1);
    atomicAdd(&g_cnt[d.z], 1);
    atomicAdd(&g_cnt[d.w], 1);
}

__global__ void k_scan1() {
    __shared__ int sd[1024];
    int tid = threadIdx.x;
    int i = blockIdx.x * 1024 + tid;
    int v = (i < NN) ? g_cnt[i] : 0;
    sd[tid] = v; __syncthreads();
    for (int off = 1; off < 1024; off <<= 1) {
        int t = (tid >= off) ? sd[tid - off] : 0;
        __syncthreads();
        sd[tid] += t; __syncthreads();
    }
    if (i < NN) g_ptr[i] = sd[tid] - v;           // block-local exclusive
    if (tid == 1023) g_bsum[blockIdx.x] = sd[1023];
}

// scan3 with inlined cross-chunk prefix (each 256-node block is inside ONE
// 1024-chunk, so it needs a single scalar prefix over g_bsum[0..chunk))
__global__ void k_scan3() {
    __shared__ int wsum[8];
    __shared__ int pre;
    int tid = threadIdx.x;
    int chunk = (blockIdx.x * 256) >> 10;
    int part = (tid < chunk) ? g_bsum[tid] : 0;    // chunk <= 97 < 256
    #pragma unroll
    for (int o = 16; o > 0; o >>= 1) part += __shfl_down_sync(0xffffffffu, part, o);
    if ((tid & 31) == 0) wsum[tid >> 5] = part;
    __syncthreads();
    if (tid == 0) {
        int s = 0;
        #pragma unroll
        for (int w = 0; w < 8; w++) s += wsum[w];
        pre = s;
    }
    __syncthreads();
    int i = blockIdx.x * 256 + tid;
    if (i < NN) {
        int p = g_ptr[i] + pre;
        g_ptr[i] = p; g_pos[i] = p;
    }
    if (i == 0) g_ptr[NN] = EE;
}

// ---- fill: scatter edges into CSR; gaussian weights from hoisted params -----
__global__ void k_fill(const int* __restrict__ ei, const float* __restrict__ attr) {
    int e = blockIdx.x * 256 + threadIdx.x;
    if (e >= EE) return;
    int s = ei[e], d = ei[EE + e];
    float a0 = attr[3*e], a1 = attr[3*e + 1], a2 = attr[3*e + 2];
    float w[11];
    #pragma unroll
    for (int t = 0; t < 11; t++) {
        float4 mu = __ldg(&g_gpar[2*t]);
        float4 iv = __ldg(&g_gpar[2*t + 1]);
        float d0 = a0 - mu.x, d1 = a1 - mu.y, d2 = a2 - mu.z;
        w[t] = __expf(-0.5f * (d0*d0*iv.x + d1*d1*iv.y + d2*d2*iv.z));
    }
    int p = atomicAdd(&g_pos[d], 1);
    uint4 v1, v2;
    v1.x = (unsigned int)s;  v1.y = f2h(w[0], w[1]); v1.z = f2h(w[2], w[3]); v1.w = f2h(w[4], w[10]);
    v2.x = (unsigned int)s;  v2.y = f2h(w[5], w[6]); v2.z = f2h(w[7], w[8]); v2.w = f2h(w[9], 0.f);
    g_m[2*(size_t)p]     = v1;            // full 32B sector per edge
    g_m[2*(size_t)p + 1] = v2;
}

// ------------- edge pass 1 (conv1 K=5 + shortcut K=1, fused): gather x -------
__global__ void k_edge1(const float* __restrict__ x) {
    int n = blockIdx.x * 8 + (threadIdx.x >> 5);
    if (n >= NN) return;
    int lane = threadIdx.x & 31;
    int beg = __ldg(&g_ptr[n]), end = __ldg(&g_ptr[n + 1]);
    float a0 = 0.f, a1 = 0.f, a2 = 0.f, a3 = 0.f, a4 = 0.f, aS = 0.f;
    int j = beg;
    for (; j + 8 <= end; j += 8) {
        uint4 m[8];
        #pragma unroll
        for (int u = 0; u < 8; u++) m[u] = __ldg(&g_m[2*(size_t)(j + u)]);
        float xv[8];
        #pragma unroll
        for (int u = 0; u < 8; u++)
            xv[u] = __ldg(x + (size_t)(int)m[u].x * C + lane);
        #pragma unroll
        for (int u = 0; u < 8; u++) {
            float2 w01 = h2f(m[u].y), w23 = h2f(m[u].z), w4s = h2f(m[u].w);
            a0 += w01.x * xv[u]; a1 += w01.y * xv[u];
            a2 += w23.x * xv[u]; a3 += w23.y * xv[u];
            a4 += w4s.x * xv[u]; aS += w4s.y * xv[u];
        }
    }
    for (; j < end; j++) {
        uint4 m = __ldg(&g_m[2*(size_t)j]);
        float xv = __ldg(x + (size_t)(int)m.x * C + lane);
        float2 w01 = h2f(m.y), w23 = h2f(m.z), w4s = h2f(m.w);
        a0 += w01.x * xv; a1 += w01.y * xv;
        a2 += w23.x * xv; a3 += w23.y * xv;
        a4 += w4s.x * xv; aS += w4s.y * xv;
    }
    float inv = 1.f / fmaxf((float)(end - beg), 1.f);
    size_t b = (size_t)n * L1 + lane;
    g_z1[b]       = a0 * inv;
    g_z1[b + 32]  = a1 * inv;
    g_z1[b + 64]  = a2 * inv;
    g_z1[b + 96]  = a3 * inv;
    g_z1[b + 128] = a4 * inv;
    g_zs[(size_t)n*C + lane] = aS * inv;
}

// -------- postA: y1 = z1@B1 + x@root1 + b1 ; ys = zs@gs + x@roots + bs -------
// + fused BN batch statistics (sum/sumsq of y1, ys)
__global__ void k_postA(const float* __restrict__ x,
                        const float* __restrict__ g1, const float* __restrict__ gs,
                        const float* __restrict__ root1, const float* __restrict__ b1,
                        const float* __restrict__ roots, const float* __restrict__ bs) {
    __shared__ float B1[L1][C];      // B1[k*32+i][o] = g1[i][k*32+o]
    __shared__ float Bs[C][C];
    __shared__ float W1[C][C];
    __shared__ float Ws[C][C];
    __shared__ float red[8][4][C];
    int tid = threadIdx.x;
    for (int idx = tid; idx < C*L1; idx += 256) {
        int i = idx / L1, r = idx % L1;
        B1[(r >> 5)*32 + i][r & 31] = g1[idx];
    }
    for (int idx = tid; idx < C*C; idx += 256) {
        Bs[idx >> 5][idx & 31] = gs[idx];
        W1[idx >> 5][idx & 31] = root1[idx];
        Ws[idx >> 5][idx & 31] = roots[idx];
    }
    __syncthreads();
    int n = blockIdx.x * 64 + (tid >> 2);
    int q = (tid & 3) * 8;
    bool valid = (n < NN);
    float acc[8]  = {0,0,0,0,0,0,0,0};
    float accs[8] = {0,0,0,0,0,0,0,0};
    if (valid) {
        {
            float4 ba = __ldg((const float4*)(b1 + q));
            float4 bb = __ldg((const float4*)(b1 + q + 4));
            acc[0]=ba.x; acc[1]=ba.y; acc[2]=ba.z; acc[3]=ba.w;
            acc[4]=bb.x; acc[5]=bb.y; acc[6]=bb.z; acc[7]=bb.w;
            float4 ca = __ldg((const float4*)(bs + q));
            float4 cb = __ldg((const float4*)(bs + q + 4));
            accs[0]=ca.x; accs[1]=ca.y; accs[2]=ca.z; accs[3]=ca.w;
            accs[4]=cb.x; accs[5]=cb.y; accs[6]=cb.z; accs[7]=cb.w;
        }
        const float* zr = g_z1 + (size_t)n * L1;
        #pragma unroll
        for (int j = 0; j < L1; j += 4) {
            float4 zv = __ldg((const float4*)(zr + j));
            #pragma unroll
            for (int jj = 0; jj < 4; jj++) {
                float s = (&zv.x)[jj];
                float4 wa = *(const float4*)&B1[j + jj][q];
                float4 wb = *(const float4*)&B1[j + jj][q + 4];
                acc[0] += s*wa.x; acc[1] += s*wa.y; acc[2] += s*wa.z; acc[3] += s*wa.w;
                acc[4] += s*wb.x; acc[5] += s*wb.y; acc[6] += s*wb.z; acc[7] += s*wb.w;
            }
        }
        const float* zsr = g_zs + (size_t)n * C;
        #pragma unroll
        for (int j = 0; j < C; j += 4) {
            float4 zv = __ldg((const float4*)(zsr + j));
            #pragma unroll
            for (int jj = 0; jj < 4; jj++) {
                float s = (&zv.x)[jj];
                float4 wa = *(const float4*)&Bs[j + jj][q];
                float4 wb = *(const float4*)&Bs[j + jj][q + 4];
                accs[0] += s*wa.x; accs[1] += s*wa.y; accs[2] += s*wa.z; accs[3] += s*wa.w;
                accs[4] += s*wb.x; accs[5] += s*wb.y; accs[6] += s*wb.z; accs[7] += s*wb.w;
            }
        }
        const float* xr = x + (size_t)n * C;
        #pragma unroll
        for (int j = 0; j < C; j += 4) {
            float4 xv = __ldg((const float4*)(xr + j));
            #pragma unroll
            for (int jj = 0; jj < 4; jj++) {
                float s = (&xv.x)[jj];
                float4 wa = *(const float4*)&W1[j + jj][q];
                float4 wb = *(const float4*)&W1[j + jj][q + 4];
                acc[0] += s*wa.x; acc[1] += s*wa.y; acc[2] += s*wa.z; acc[3] += s*wa.w;
                acc[4] += s*wb.x; acc[5] += s*wb.y; acc[6] += s*wb.z; acc[7] += s*wb.w;
                float4 va = *(const float4*)&Ws[j + jj][q];
                float4 vb = *(const float4*)&Ws[j + jj][q + 4];
                accs[0] += s*va.x; accs[1] += s*va.y; accs[2] += s*va.z; accs[3] += s*va.w;
                accs[4] += s*vb.x; accs[5] += s*vb.y; accs[6] += s*vb.z; accs[7] += s*vb.w;
            }
        }
        size_t b = (size_t)n * C + q;
        *(float4*)(g_y1 + b)     = make_float4(acc[0], acc[1], acc[2], acc[3]);
        *(float4*)(g_y1 + b + 4) = make_float4(acc[4], acc[5], acc[6], acc[7]);
        *(float4*)(g_ys + b)     = make_float4(accs[0], accs[1], accs[2], accs[3]);
        *(float4*)(g_ys + b + 4) = make_float4(accs[4], accs[5], accs[6], accs[7]);
    }
    // ---- fused BN statistics: shfl butterfly over same-column lanes ----
    float sq[8], sqs[8];
    #pragma unroll
    for (int i = 0; i < 8; i++) { sq[i] = acc[i]*acc[i]; sqs[i] = accs[i]*accs[i]; }
    #pragma unroll
    for (int o = 4; o < 32; o <<= 1) {
        #pragma unroll
        for (int i = 0; i < 8; i++) {
            acc[i]  += __shfl_xor_sync(0xffffffffu, acc[i],  o);
            sq[i]   += __shfl_xor_sync(0xffffffffu, sq[i],   o);
            accs[i] += __shfl_xor_sync(0xffffffffu, accs[i], o);
            sqs[i]  += __shfl_xor_sync(0xffffffffu, sqs[i],  o);
        }
    }
    int lane = tid & 31, w = tid >> 5;
    if (lane < 4) {
        #pragma unroll
        for (int i = 0; i < 8; i++) {
            red[w][0][lane*8 + i] = acc[i];
            red[w][1][lane*8 + i] = sq[i];
            red[w][2][lane*8 + i] = accs[i];
            red[w][3][lane*8 + i] = sqs[i];
        }
    }
    __syncthreads();
    if (tid < 128) {
        float t = 0.f;
        #pragma unroll
        for (int ww = 0; ww < 8; ww++) t += red[ww][tid >> 5][tid & 31];
        atomicAdd(&g_stat[tid], t);
    }
}

// --------- prepB: h1 = elu(BN1(y1)); BN consts recomputed per block ----------
__global__ void k_prepB(const float* __restrict__ gam1, const float* __restrict__ bet1) {
    __shared__ float sc[C], sh[C];
    int tid = threadIdx.x;
    if (tid < 32) {
        const float invn = 1.f / (float)NN;
        float m = g_stat[tid] * invn;
        float v = g_stat[32 + tid] * invn - m*m;
        float s = __ldg(gam1 + tid) * rsqrtf(v + BNE);
        sc[tid] = s; sh[tid] = __ldg(bet1 + tid) - m*s;
    }
    __syncthreads();
    int i4 = blockIdx.x * 256 + tid;             // group of 4 elements
    if (i4 >= NN*C/4) return;
    int c4 = (i4 & 7) * 4;
    float4 y   = *(const float4*)(g_y1 + (size_t)i4 * 4);
    float4 scv = *(const float4*)&sc[c4];
    float4 shv = *(const float4*)&sh[c4];
    float v0 = y.x*scv.x + shv.x, v1 = y.y*scv.y + shv.y;
    float v2 = y.z*scv.z + shv.z, v3 = y.w*scv.w + shv.w;
    float4 h4;
    h4.x = (v0 > 0.f) ? v0 : expm1f(v0);
    h4.y = (v1 > 0.f) ? v1 : expm1f(v1);
    h4.z = (v2 > 0.f) ? v2 : expm1f(v2);
    h4.w = (v3 > 0.f) ? v3 : expm1f(v3);
    *(float4*)(g_h1 + (size_t)i4 * 4) = h4;
}

// ------------------------ edge pass 2 (conv2 K=5): gather h1 -----------------
__global__ void k_edge2() {
    int n = blockIdx.x * 8 + (threadIdx.x >> 5);
    if (n >= NN) return;
    int lane = threadIdx.x & 31;
    int beg = __ldg(&g_ptr[n]), end = __ldg(&g_ptr[n + 1]);
    float a0 = 0.f, a1 = 0.f, a2 = 0.f, a3 = 0.f, a4 = 0.f;
    int j = beg;
    for (; j + 8 <= end; j += 8) {
        uint4 m[8];
        #pragma unroll
        for (int u = 0; u < 8; u++) m[u] = __ldg(&g_m[2*(size_t)(j + u) + 1]);
        float hv[8];
        #pragma unroll
        for (int u = 0; u < 8; u++)
            hv[u] = __ldg(&g_h1[(size_t)(int)m[u].x * C + lane]);
        #pragma unroll
        for (int u = 0; u < 8; u++) {
            float2 w01 = h2f(m[u].y), w23 = h2f(m[u].z), w4x = h2f(m[u].w);
            a0 += w01.x * hv[u]; a1 += w01.y * hv[u];
            a2 += w23.x * hv[u]; a3 += w23.y * hv[u];
            a4 += w4x.x * hv[u];
        }
    }
    for (; j < end; j++) {
        uint4 m = __ldg(&g_m[2*(size_t)j + 1]);
        float hv = __ldg(&g_h1[(size_t)(int)m.x * C + lane]);
        float2 w01 = h2f(m.y), w23 = h2f(m.z), w4x = h2f(m.w);
        a0 += w01.x * hv; a1 += w01.y * hv;
        a2 += w23.x * hv; a3 += w23.y * hv;
        a4 += w4x.x * hv;
    }
    float inv = 1.f / fmaxf((float)(end - beg), 1.f);
    size_t b = (size_t)n * L1 + lane;
    g_z2[b]       = a0 * inv;
    g_z2[b + 32]  = a1 * inv;
    g_z2[b + 64]  = a2 * inv;
    g_z2[b + 96]  = a3 * inv;
    g_z2[b + 128] = a4 * inv;
}

// ------------- postB: y2 = z2@B2 + h1@root2 + b2 ; + fused BN stats ----------
__global__ void k_postB(const float* __restrict__ g2, const float* __restrict__ root2,
                        const float* __restrict__ b2) {
    __shared__ float B2[L1][C];
    __shared__ float W2[C][C];
    __shared__ float red[8][2][C];
    int tid = threadIdx.x;
    for (int idx = tid; idx < C*L1; idx += 256) {
        int i = idx / L1, r = idx % L1;
        B2[(r >> 5)*32 + i][r & 31] = g2[idx];
    }
    for (int idx = tid; idx < C*C; idx += 256)
        W2[idx >> 5][idx & 31] = root2[idx];
    __syncthreads();
    int n = blockIdx.x * 64 + (tid >> 2);
    int q = (tid & 3) * 8;
    bool valid = (n < NN);
    float acc[8] = {0,0,0,0,0,0,0,0};
    if (valid) {
        {
            float4 ba = __ldg((const float4*)(b2 + q));
            float4 bb = __ldg((const float4*)(b2 + q + 4));
            acc[0]=ba.x; acc[1]=ba.y; acc[2]=ba.z; acc[3]=ba.w;
            acc[4]=bb.x; acc[5]=bb.y; acc[6]=bb.z; acc[7]=bb.w;
        }
        const float* zr = g_z2 + (size_t)n * L1;
        #pragma unroll
        for (int j = 0; j < L1; j += 4) {
            float4 zv = __ldg((const float4*)(zr + j));
            #pragma unroll
            for (int jj = 0; jj < 4; jj++) {
                float s = (&zv.x)[jj];
                float4 wa = *(const float4*)&B2[j + jj][q];
                float4 wb = *(const float4*)&B2[j + jj][q + 4];
                acc[0] += s*wa.x; acc[1] += s*wa.y; acc[2] += s*wa.z; acc[3] += s*wa.w;
                acc[4] += s*wb.x; acc[5] += s*wb.y; acc[6] += s*wb.z; acc[7] += s*wb.w;
            }
        }
        const float* hr = g_h1 + (size_t)n * C;
        #pragma unroll
        for (int j = 0; j < C; j += 4) {
            float4 hv = __ldg((const float4*)(hr + j));
            #pragma unroll
            for (int jj = 0; jj < 4; jj++) {
                float s = (&hv.x)[jj];
                float4 wa = *(const float4*)&W2[j + jj][q];
                float4 wb = *(const float4*)&W2[j + jj][q + 4];
                acc[0] += s*wa.x; acc[1] += s*wa.y; acc[2] += s*wa.z; acc[3] += s*wa.w;
                acc[4] += s*wb.x; acc[5] += s*wb.y; acc[6] += s*wb.z; acc[7] += s*wb.w;
            }
        }
        size_t b = (size_t)n * C + q;
        *(float4*)(g_y2 + b)     = make_float4(acc[0], acc[1], acc[2], acc[3]);
        *(float4*)(g_y2 + b + 4) = make_float4(acc[4], acc[5], acc[6], acc[7]);
    }
    float sq[8];
    #pragma unroll
    for (int i = 0; i < 8; i++) sq[i] = acc[i]*acc[i];
    #pragma unroll
    for (int o = 4; o < 32; o <<= 1) {
        #pragma unroll
        for (int i = 0; i < 8; i++) {
            acc[i] += __shfl_xor_sync(0xffffffffu, acc[i], o);
            sq[i]  += __shfl_xor_sync(0xffffffffu, sq[i],  o);
        }
    }
    int lane = tid & 31, w = tid >> 5;
    if (lane < 4) {
        #pragma unroll
        for (int i = 0; i < 8; i++) {
            red[w][0][lane*8 + i] = acc[i];
            red[w][1][lane*8 + i] = sq[i];
        }
    }
    __syncthreads();
    if (tid < 64) {
        float t = 0.f;
        #pragma unroll
        for (int ww = 0; ww < 8; ww++) t += red[ww][tid >> 5][tid & 31];
        atomicAdd(&g_stat[128 + tid], t);
    }
}

// -------- final: out = elu(BN2(y2) + BNs(ys)); consts recomputed per block ---
__global__ void k_final(float* __restrict__ out,
                        const float* __restrict__ gam2, const float* __restrict__ bet2,
                        const float* __restrict__ gams, const float* __restrict__ bets) {
    __shared__ float c2[C], s2[C], cs[C], ss[C];
    int tid = threadIdx.x;
    if (tid < 32) {
        const float invn = 1.f / (float)NN;
        float m2 = g_stat[128 + tid] * invn;
        float v2 = g_stat[160 + tid] * invn - m2*m2;
        float sc2 = __ldg(gam2 + tid) * rsqrtf(v2 + BNE);
        c2[tid] = sc2; s2[tid] = __ldg(bet2 + tid) - m2*sc2;
        float ms = g_stat[64 + tid] * invn;
        float vs = g_stat[96 + tid] * invn - ms*ms;
        float scs = __ldg(gams + tid) * rsqrtf(vs + BNE);
        cs[tid] = scs; ss[tid] = __ldg(bets + tid) - ms*scs;
    }
    __syncthreads();
    int i = blockIdx.x * 256 + tid;
    if (i >= NN*C) return;
    int c = i & 31;
    float v2 = g_y2[i] * c2[c] + s2[c];
    float vs = g_ys[i] * cs[c] + ss[c];
    float h = v2 + vs;
    out[i] = (h > 0.f) ? h : expm1f(h);
}

// ------------------------------------------------------------------------------
extern "C" void kernel_launch(void* const* d_in, const int* in_sizes, int n_in,
                              void* d_out, int out_size) {
    (void)in_sizes; (void)n_in; (void)out_size;
    const float* x     = (const float*)d_in[0];
    const int*   ei    = (const int*)  d_in[1];
    const float* attr  = (const float*)d_in[2];
    const float* g1    = (const float*)d_in[3];
    const float* mu1   = (const float*)d_in[4];
    const float* sg1   = (const float*)d_in[5];
    const float* root1 = (const float*)d_in[6];
    const float* b1    = (const float*)d_in[7];
    const float* gam1  = (const float*)d_in[8];
    const float* bet1  = (const float*)d_in[9];
    const float* g2    = (const float*)d_in[10];
    const float* mu2   = (const float*)d_in[11];
    const float* sg2   = (const float*)d_in[12];
    const float* root2 = (const float*)d_in[13];
    const float* b2    = (const float*)d_in[14];
    const float* gam2  = (const float*)d_in[15];
    const float* bet2  = (const float*)d_in[16];
    const float* gs    = (const float*)d_in[17];
    const float* mus   = (const float*)d_in[18];
    const float* sgs   = (const float*)d_in[19];
    const float* roots = (const float*)d_in[20];
    const float* bs    = (const float*)d_in[21];
    const float* gams  = (const float*)d_in[22];
    const float* bets  = (const float*)d_in[23];
    float* out = (float*)d_out;

    const int nb_scan = (NN + 1023) / 1024;

    k_zg   <<<(NN + 255)/256, 256>>>(mu1, sg1, mu2, sg2, mus, sgs);
    k_count<<<(EE/4 + 255)/256, 256>>>(ei);
    k_scan1<<<nb_scan, 1024>>>();
    k_scan3<<<(NN + 255)/256, 256>>>();
    k_fill <<<(EE + 255)/256, 256>>>(ei, attr);
    k_edge1<<<(NN + 7)/8,     256>>>(x);
    k_postA<<<(NN + 63)/64,   256>>>(x, g1, gs, root1, b1, roots, bs);
    k_prepB<<<(NN*C/4 + 255)/256, 256>>>(gam1, bet1);
    k_edge2<<<(NN + 7)/8,     256>>>();
    k_postB<<<(NN + 63)/64,   256>>>(g2, root2, b2);
    k_final<<<(NN*C + 255)/256, 256>>>(out, gam2, bet2, gams, bets);
}

// round 11
// speedup vs baseline: 1.2541x; 1.0009x over previous
#include <cuda_runtime.h>
#include <cuda_fp16.h>
#include <math.h>

#define NN   100000
#define EE   1600000
#define C    32
#define KK   5
#define L1   (KK*C)          // 160
#define EPSV 1e-15f
#define BNE  1e-5f

// ------------------------- device scratch (no allocs) -------------------------
__device__ float  g_z1 [(size_t)NN*L1];
__device__ float  g_zs [(size_t)NN*C];
__device__ float  g_z2 [(size_t)NN*L1];
__device__ float  g_y1 [(size_t)NN*C];
__device__ float  g_ys [(size_t)NN*C];
__device__ float  g_y2 [(size_t)NN*C];
__device__ float  g_h1 [(size_t)NN*C];
__device__ int    g_cnt[NN];
__device__ int    g_ptr[NN+1];
__device__ int    g_pos[NN];
__device__ int    g_bsum[128];
__device__ float  g_stat[8*C];     // [sum_y1, sq_y1, sum_ys, sq_ys, sum_y2, sq_y2, -, -]
__device__ float4 g_gpar[22];      // 11 gaussian comps: {mu0,mu1,mu2,_},{i0,i1,i2,_}
// per-CSR-edge compressed meta, interleaved 32B (full-sector scatter writes):
//   g_m[2p]   = {src:int, half2(w1_0,w1_1), half2(w1_2,w1_3), half2(w1_4, ws)}
//   g_m[2p+1] = {src:int, half2(w2_0,w2_1), half2(w2_2,w2_3), half2(w2_4, 0)}
__device__ uint4  g_m[(size_t)2*EE];

__device__ __forceinline__ float2 h2f(unsigned int u) {
    __half2 h = *reinterpret_cast<__half2*>(&u);
    return __half22float2(h);
}
__device__ __forceinline__ unsigned int f2h(float a, float b) {
    __half2 h = __floats2half2_rn(a, b);
    return *reinterpret_cast<unsigned int*>(&h);
}

// ---- packed fp32x2 FMA helpers (FFMA2: 2 full-precision MACs / instr) -------
__device__ __forceinline__ unsigned long long fpack2(float lo, float hi) {
    unsigned long long r;
    asm("mov.b64 %0, {%1, %2};" : "=l"(r) : "f"(lo), "f"(hi));
    return r;
}
__device__ __forceinline__ unsigned long long fbcast2(float s) {
    unsigned long long r;
    asm("mov.b64 %0, {%1, %1};" : "=l"(r) : "f"(s));
    return r;
}
__device__ __forceinline__ void fma2(unsigned long long& d,
                                     unsigned long long a, unsigned long long b) {
    asm("fma.rn.f32x2 %0, %1, %2, %0;" : "+l"(d) : "l"(a), "l"(b));
}
__device__ __forceinline__ float2 funpack2(unsigned long long v) {
    float lo, hi;
    asm("mov.b64 {%0, %1}, %2;" : "=f"(lo), "=f"(hi) : "l"(v));
    return make_float2(lo, hi);
}

// ------------------- zero scratch + gaussian param prep ----------------------
__global__ void k_zg(const float* __restrict__ mu1, const float* __restrict__ sg1,
                     const float* __restrict__ mu2, const float* __restrict__ sg2,
                     const float* __restrict__ mus, const float* __restrict__ sgs) {
    int i = blockIdx.x * 256 + threadIdx.x;
    if (i < NN)   g_cnt[i] = 0;
    if (i < 8*C)  g_stat[i] = 0.f;
    if (i < 11) {
        const float* mu; const float* sg; int k;
        if (i < 5)       { mu = mu1; sg = sg1; k = i; }
        else if (i < 10) { mu = mu2; sg = sg2; k = i - 5; }
        else             { mu = mus; sg = sgs; k = 0; }
        float m0 = mu[3*k], m1 = mu[3*k+1], m2 = mu[3*k+2];
        float s0 = sg[3*k], s1 = sg[3*k+1], s2 = sg[3*k+2];
        g_gpar[2*i]     = make_float4(m0, m1, m2, 0.f);
        g_gpar[2*i + 1] = make_float4(1.f/(EPSV + s0*s0), 1.f/(EPSV + s1*s1), 1.f/(EPSV + s2*s2), 0.f);
    }
}

// ------------------------------ CSR build ------------------------------------
__global__ void k_count(const int* __restrict__ ei) {
    int idx = blockIdx.x * 256 + threadIdx.x;
    if (idx * 4 >= EE) return;
    int4 d = __ldg((const int4*)(ei + EE) + idx);
    atomicAdd(&g_cnt[d.x], 1);
    atomicAdd(&g_cnt[d.y], 1);
    atomicAdd(&g_cnt[d.z], 1);
    atomicAdd(&g_cnt[d.w], 1);
}

__global__ void k_scan1() {
    __shared__ int sd[1024];
    int tid = threadIdx.x;
    int i = blockIdx.x * 1024 + tid;
    int v = (i < NN) ? g_cnt[i] : 0;
    sd[tid] = v; __syncthreads();
    for (int off = 1; off < 1024; off <<= 1) {
        int t = (tid >= off) ? sd[tid - off] : 0;
        __syncthreads();
        sd[tid] += t; __syncthreads();
    }
    if (i < NN) g_ptr[i] = sd[tid] - v;           // block-local exclusive
    if (tid == 1023) g_bsum[blockIdx.x] = sd[1023];
}

// scan3 with inlined cross-chunk prefix
__global__ void k_scan3() {
    __shared__ int wsum[8];
    __shared__ int pre;
    int tid = threadIdx.x;
    int chunk = (blockIdx.x * 256) >> 10;
    int part = (tid < chunk) ? g_bsum[tid] : 0;    // chunk <= 97 < 256
    #pragma unroll
    for (int o = 16; o > 0; o >>= 1) part += __shfl_down_sync(0xffffffffu, part, o);
    if ((tid & 31) == 0) wsum[tid >> 5] = part;
    __syncthreads();
    if (tid == 0) {
        int s = 0;
        #pragma unroll
        for (int w = 0; w < 8; w++) s += wsum[w];
        pre = s;
    }
    __syncthreads();
    int i = blockIdx.x * 256 + tid;
    if (i < NN) {
        int p = g_ptr[i] + pre;
        g_ptr[i] = p; g_pos[i] = p;
    }
    if (i == 0) g_ptr[NN] = EE;
}

// ---- fill: scatter edges into CSR; gaussian weights from hoisted params -----
__global__ void k_fill(const int* __restrict__ ei, const float* __restrict__ attr) {
    int e = blockIdx.x * 256 + threadIdx.x;
    if (e >= EE) return;
    int s = ei[e], d = ei[EE + e];
    float a0 = attr[3*e], a1 = attr[3*e + 1], a2 = attr[3*e + 2];
    float w[11];
    #pragma unroll
    for (int t = 0; t < 11; t++) {
        float4 mu = __ldg(&g_gpar[2*t]);
        float4 iv = __ldg(&g_gpar[2*t + 1]);
        float d0 = a0 - mu.x, d1 = a1 - mu.y, d2 = a2 - mu.z;
        w[t] = __expf(-0.5f * (d0*d0*iv.x + d1*d1*iv.y + d2*d2*iv.z));
    }
    int p = atomicAdd(&g_pos[d], 1);
    uint4 v1, v2;
    v1.x = (unsigned int)s;  v1.y = f2h(w[0], w[1]); v1.z = f2h(w[2], w[3]); v1.w = f2h(w[4], w[10]);
    v2.x = (unsigned int)s;  v2.y = f2h(w[5], w[6]); v2.z = f2h(w[7], w[8]); v2.w = f2h(w[9], 0.f);
    g_m[2*(size_t)p]     = v1;            // full 32B sector per edge
    g_m[2*(size_t)p + 1] = v2;
}

// ------------- edge pass 1 (conv1 K=5 + shortcut K=1, fused): gather x -------
__global__ void k_edge1(const float* __restrict__ x) {
    int n = blockIdx.x * 8 + (threadIdx.x >> 5);
    if (n >= NN) return;
    int lane = threadIdx.x & 31;
    int beg = __ldg(&g_ptr[n]), end = __ldg(&g_ptr[n + 1]);
    float a0 = 0.f, a1 = 0.f, a2 = 0.f, a3 = 0.f, a4 = 0.f, aS = 0.f;
    int j = beg;
    for (; j + 8 <= end; j += 8) {
        uint4 m[8];
        #pragma unroll
        for (int u = 0; u < 8; u++) m[u] = __ldg(&g_m[2*(size_t)(j + u)]);
        float xv[8];
        #pragma unroll
        for (int u = 0; u < 8; u++)
            xv[u] = __ldg(x + (size_t)(int)m[u].x * C + lane);
        #pragma unroll
        for (int u = 0; u < 8; u++) {
            float2 w01 = h2f(m[u].y), w23 = h2f(m[u].z), w4s = h2f(m[u].w);
            a0 += w01.x * xv[u]; a1 += w01.y * xv[u];
            a2 += w23.x * xv[u]; a3 += w23.y * xv[u];
            a4 += w4s.x * xv[u]; aS += w4s.y * xv[u];
        }
    }
    for (; j < end; j++) {
        uint4 m = __ldg(&g_m[2*(size_t)j]);
        float xv = __ldg(x + (size_t)(int)m.x * C + lane);
        float2 w01 = h2f(m.y), w23 = h2f(m.z), w4s = h2f(m.w);
        a0 += w01.x * xv; a1 += w01.y * xv;
        a2 += w23.x * xv; a3 += w23.y * xv;
        a4 += w4s.x * xv; aS += w4s.y * xv;
    }
    float inv = 1.f / fmaxf((float)(end - beg), 1.f);
    size_t b = (size_t)n * L1 + lane;
    g_z1[b]       = a0 * inv;
    g_z1[b + 32]  = a1 * inv;
    g_z1[b + 64]  = a2 * inv;
    g_z1[b + 96]  = a3 * inv;
    g_z1[b + 128] = a4 * inv;
    g_zs[(size_t)n*C + lane] = aS * inv;
}

// -------- postA: y1 = z1@B1 + x@root1 + b1 ; ys = zs@gs + x@roots + bs -------
// packed f32x2 FMA inner loops; + fused BN batch statistics
__global__ void k_postA(const float* __restrict__ x,
                        const float* __restrict__ g1, const float* __restrict__ gs,
                        const float* __restrict__ root1, const float* __restrict__ b1,
                        const float* __restrict__ roots, const float* __restrict__ bs) {
    __shared__ float B1[L1][C];      // B1[k*32+i][o] = g1[i][k*32+o]
    __shared__ float Bs[C][C];
    __shared__ float W1[C][C];
    __shared__ float Ws[C][C];
    __shared__ float red[8][4][C];
    int tid = threadIdx.x;
    for (int idx = tid; idx < C*L1; idx += 256) {
        int i = idx / L1, r = idx % L1;
        B1[(r >> 5)*32 + i][r & 31] = g1[idx];
    }
    for (int idx = tid; idx < C*C; idx += 256) {
        Bs[idx >> 5][idx & 31] = gs[idx];
        W1[idx >> 5][idx & 31] = root1[idx];
        Ws[idx >> 5][idx & 31] = roots[idx];
    }
    __syncthreads();
    int n = blockIdx.x * 64 + (tid >> 2);
    int q = (tid & 3) * 8;
    bool valid = (n < NN);
    unsigned long long accp[4]  = {0,0,0,0};
    unsigned long long accsp[4] = {0,0,0,0};
    if (valid) {
        {
            float4 ba = __ldg((const float4*)(b1 + q));
            float4 bb = __ldg((const float4*)(b1 + q + 4));
            accp[0] = fpack2(ba.x, ba.y); accp[1] = fpack2(ba.z, ba.w);
            accp[2] = fpack2(bb.x, bb.y); accp[3] = fpack2(bb.z, bb.w);
            float4 ca = __ldg((const float4*)(bs + q));
            float4 cb = __ldg((const float4*)(bs + q + 4));
            accsp[0] = fpack2(ca.x, ca.y); accsp[1] = fpack2(ca.z, ca.w);
            accsp[2] = fpack2(cb.x, cb.y); accsp[3] = fpack2(cb.z, cb.w);
        }
        const float* zr = g_z1 + (size_t)n * L1;
        #pragma unroll
        for (int j = 0; j < L1; j += 4) {
            float4 zv = __ldg((const float4*)(zr + j));
            #pragma unroll
            for (int jj = 0; jj < 4; jj++) {
                unsigned long long sp = fbcast2((&zv.x)[jj]);
                const unsigned long long* wp =
                    (const unsigned long long*)&B1[j + jj][q];
                fma2(accp[0], wp[0], sp); fma2(accp[1], wp[1], sp);
                fma2(accp[2], wp[2], sp); fma2(accp[3], wp[3], sp);
            }
        }
        const float* zsr = g_zs + (size_t)n * C;
        #pragma unroll
        for (int j = 0; j < C; j += 4) {
            float4 zv = __ldg((const float4*)(zsr + j));
            #pragma unroll
            for (int jj = 0; jj < 4; jj++) {
                unsigned long long sp = fbcast2((&zv.x)[jj]);
                const unsigned long long* wp =
                    (const unsigned long long*)&Bs[j + jj][q];
                fma2(accsp[0], wp[0], sp); fma2(accsp[1], wp[1], sp);
                fma2(accsp[2], wp[2], sp); fma2(accsp[3], wp[3], sp);
            }
        }
        const float* xr = x + (size_t)n * C;
        #pragma unroll
        for (int j = 0; j < C; j += 4) {
            float4 xv = __ldg((const float4*)(xr + j));
            #pragma unroll
            for (int jj = 0; jj < 4; jj++) {
                unsigned long long sp = fbcast2((&xv.x)[jj]);
                const unsigned long long* wp =
                    (const unsigned long long*)&W1[j + jj][q];
                fma2(accp[0], wp[0], sp); fma2(accp[1], wp[1], sp);
                fma2(accp[2], wp[2], sp); fma2(accp[3], wp[3], sp);
                const unsigned long long* vp =
                    (const unsigned long long*)&Ws[j + jj][q];
                fma2(accsp[0], vp[0], sp); fma2(accsp[1], vp[1], sp);
                fma2(accsp[2], vp[2], sp); fma2(accsp[3], vp[3], sp);
            }
        }
    }
    float acc[8], accs[8];
    #pragma unroll
    for (int i = 0; i < 4; i++) {
        float2 a = funpack2(accp[i]);  acc[2*i] = a.x;  acc[2*i+1] = a.y;
        float2 b = funpack2(accsp[i]); accs[2*i] = b.x; accs[2*i+1] = b.y;
    }
    if (valid) {
        size_t b = (size_t)n * C + q;
        *(float4*)(g_y1 + b)     = make_float4(acc[0], acc[1], acc[2], acc[3]);
        *(float4*)(g_y1 + b + 4) = make_float4(acc[4], acc[5], acc[6], acc[7]);
        *(float4*)(g_ys + b)     = make_float4(accs[0], accs[1], accs[2], accs[3]);
        *(float4*)(g_ys + b + 4) = make_float4(accs[4], accs[5], accs[6], accs[7]);
    } else {
        #pragma unroll
        for (int i = 0; i < 8; i++) { acc[i] = 0.f; accs[i] = 0.f; }
    }
    // ---- fused BN statistics: shfl butterfly over same-column lanes ----
    float sq[8], sqs[8];
    #pragma unroll
    for (int i = 0; i < 8; i++) { sq[i] = acc[i]*acc[i]; sqs[i] = accs[i]*accs[i]; }
    #pragma unroll
    for (int o = 4; o < 32; o <<= 1) {
        #pragma unroll
        for (int i = 0; i < 8; i++) {
            acc[i]  += __shfl_xor_sync(0xffffffffu, acc[i],  o);
            sq[i]   += __shfl_xor_sync(0xffffffffu, sq[i],   o);
            accs[i] += __shfl_xor_sync(0xffffffffu, accs[i], o);
            sqs[i]  += __shfl_xor_sync(0xffffffffu, sqs[i],  o);
        }
    }
    int lane = tid & 31, w = tid >> 5;
    if (lane < 4) {
        #pragma unroll
        for (int i = 0; i < 8; i++) {
            red[w][0][lane*8 + i] = acc[i];
            red[w][1][lane*8 + i] = sq[i];
            red[w][2][lane*8 + i] = accs[i];
            red[w][3][lane*8 + i] = sqs[i];
        }
    }
    __syncthreads();
    if (tid < 128) {
        float t = 0.f;
        #pragma unroll
        for (int ww = 0; ww < 8; ww++) t += red[ww][tid >> 5][tid & 31];
        atomicAdd(&g_stat[tid], t);
    }
}

// --------- prepB: h1 = elu(BN1(y1)); BN consts recomputed per block ----------
__global__ void k_prepB(const float* __restrict__ gam1, const float* __restrict__ bet1) {
    __shared__ float sc[C], sh[C];
    int tid = threadIdx.x;
    if (tid < 32) {
        const float invn = 1.f / (float)NN;
        float m = g_stat[tid] * invn;
        float v = g_stat[32 + tid] * invn - m*m;
        float s = __ldg(gam1 + tid) * rsqrtf(v + BNE);
        sc[tid] = s; sh[tid] = __ldg(bet1 + tid) - m*s;
    }
    __syncthreads();
    int i4 = blockIdx.x * 256 + tid;             // group of 4 elements
    if (i4 >= NN*C/4) return;
    int c4 = (i4 & 7) * 4;
    float4 y   = *(const float4*)(g_y1 + (size_t)i4 * 4);
    float4 scv = *(const float4*)&sc[c4];
    float4 shv = *(const float4*)&sh[c4];
    float v0 = y.x*scv.x + shv.x, v1 = y.y*scv.y + shv.y;
    float v2 = y.z*scv.z + shv.z, v3 = y.w*scv.w + shv.w;
    float4 h4;
    h4.x = (v0 > 0.f) ? v0 : expm1f(v0);
    h4.y = (v1 > 0.f) ? v1 : expm1f(v1);
    h4.z = (v2 > 0.f) ? v2 : expm1f(v2);
    h4.w = (v3 > 0.f) ? v3 : expm1f(v3);
    *(float4*)(g_h1 + (size_t)i4 * 4) = h4;
}

// ------------------------ edge pass 2 (conv2 K=5): gather h1 -----------------
__global__ void k_edge2() {
    int n = blockIdx.x * 8 + (threadIdx.x >> 5);
    if (n >= NN) return;
    int lane = threadIdx.x & 31;
    int beg = __ldg(&g_ptr[n]), end = __ldg(&g_ptr[n + 1]);
    float a0 = 0.f, a1 = 0.f, a2 = 0.f, a3 = 0.f, a4 = 0.f;
    int j = beg;
    for (; j + 8 <= end; j += 8) {
        uint4 m[8];
        #pragma unroll
        for (int u = 0; u < 8; u++) m[u] = __ldg(&g_m[2*(size_t)(j + u) + 1]);
        float hv[8];
        #pragma unroll
        for (int u = 0; u < 8; u++)
            hv[u] = __ldg(&g_h1[(size_t)(int)m[u].x * C + lane]);
        #pragma unroll
        for (int u = 0; u < 8; u++) {
            float2 w01 = h2f(m[u].y), w23 = h2f(m[u].z), w4x = h2f(m[u].w);
            a0 += w01.x * hv[u]; a1 += w01.y * hv[u];
            a2 += w23.x * hv[u]; a3 += w23.y * hv[u];
            a4 += w4x.x * hv[u];
        }
    }
    for (; j < end; j++) {
        uint4 m = __ldg(&g_m[2*(size_t)j + 1]);
        float hv = __ldg(&g_h1[(size_t)(int)m.x * C + lane]);
        float2 w01 = h2f(m.y), w23 = h2f(m.z), w4x = h2f(m.w);
        a0 += w01.x * hv; a1 += w01.y * hv;
        a2 += w23.x * hv; a3 += w23.y * hv;
        a4 += w4x.x * hv;
    }
    float inv = 1.f / fmaxf((float)(end - beg), 1.f);
    size_t b = (size_t)n * L1 + lane;
    g_z2[b]       = a0 * inv;
    g_z2[b + 32]  = a1 * inv;
    g_z2[b + 64]  = a2 * inv;
    g_z2[b + 96]  = a3 * inv;
    g_z2[b + 128] = a4 * inv;
}

// ------------- postB: y2 = z2@B2 + h1@root2 + b2 ; + fused BN stats ----------
__global__ void k_postB(const float* __restrict__ g2, const float* __restrict__ root2,
                        const float* __restrict__ b2) {
    __shared__ float B2[L1][C];
    __shared__ float W2[C][C];
    __shared__ float red[8][2][C];
    int tid = threadIdx.x;
    for (int idx = tid; idx < C*L1; idx += 256) {
        int i = idx / L1, r = idx % L1;
        B2[(r >> 5)*32 + i][r & 31] = g2[idx];
    }
    for (int idx = tid; idx < C*C; idx += 256)
        W2[idx >> 5][idx & 31] = root2[idx];
    __syncthreads();
    int n = blockIdx.x * 64 + (tid >> 2);
    int q = (tid & 3) * 8;
    bool valid = (n < NN);
    unsigned long long accp[4] = {0,0,0,0};
    if (valid) {
        {
            float4 ba = __ldg((const float4*)(b2 + q));
            float4 bb = __ldg((const float4*)(b2 + q + 4));
            accp[0] = fpack2(ba.x, ba.y); accp[1] = fpack2(ba.z, ba.w);
            accp[2] = fpack2(bb.x, bb.y); accp[3] = fpack2(bb.z, bb.w);
        }
        const float* zr = g_z2 + (size_t)n * L1;
        #pragma unroll
        for (int j = 0; j < L1; j += 4) {
            float4 zv = __ldg((const float4*)(zr + j));
            #pragma unroll
            for (int jj = 0; jj < 4; jj++) {
                unsigned long long sp = fbcast2((&zv.x)[jj]);
                const unsigned long long* wp =
                    (const unsigned long long*)&B2[j + jj][q];
                fma2(accp[0], wp[0], sp); fma2(accp[1], wp[1], sp);
                fma2(accp[2], wp[2], sp); fma2(accp[3], wp[3], sp);
            }
        }
        const float* hr = g_h1 + (size_t)n * C;
        #pragma unroll
        for (int j = 0; j < C; j += 4) {
            float4 hv = __ldg((const float4*)(hr + j));
            #pragma unroll
            for (int jj = 0; jj < 4; jj++) {
                unsigned long long sp = fbcast2((&hv.x)[jj]);
                const unsigned long long* wp =
                    (const unsigned long long*)&W2[j + jj][q];
                fma2(accp[0], wp[0], sp); fma2(accp[1], wp[1], sp);
                fma2(accp[2], wp[2], sp); fma2(accp[3], wp[3], sp);
            }
        }
    }
    float acc[8];
    #pragma unroll
    for (int i = 0; i < 4; i++) {
        float2 a = funpack2(accp[i]); acc[2*i] = a.x; acc[2*i+1] = a.y;
    }
    if (valid) {
        size_t b = (size_t)n * C + q;
        *(float4*)(g_y2 + b)     = make_float4(acc[0], acc[1], acc[2], acc[3]);
        *(float4*)(g_y2 + b + 4) = make_float4(acc[4], acc[5], acc[6], acc[7]);
    } else {
        #pragma unroll
        for (int i = 0; i < 8; i++) acc[i] = 0.f;
    }
    float sq[8];
    #pragma unroll
    for (int i = 0; i < 8; i++) sq[i] = acc[i]*acc[i];
    #pragma unroll
    for (int o = 4; o < 32; o <<= 1) {
        #pragma unroll
        for (int i = 0; i < 8; i++) {
            acc[i] += __shfl_xor_sync(0xffffffffu, acc[i], o);
            sq[i]  += __shfl_xor_sync(0xffffffffu, sq[i],  o);
        }
    }
    int lane = tid & 31, w = tid >> 5;
    if (lane < 4) {
        #pragma unroll
        for (int i = 0; i < 8; i++) {
            red[w][0][lane*8 + i] = acc[i];
            red[w][1][lane*8 + i] = sq[i];
        }
    }
    __syncthreads();
    if (tid < 64) {
        float t = 0.f;
        #pragma unroll
        for (int ww = 0; ww < 8; ww++) t += red[ww][tid >> 5][tid & 31];
        atomicAdd(&g_stat[128 + tid], t);
    }
}

// -------- final: out = elu(BN2(y2) + BNs(ys)); consts recomputed per block ---
__global__ void k_final(float* __restrict__ out,
                        const float* __restrict__ gam2, const float* __restrict__ bet2,
                        const float* __restrict__ gams, const float* __restrict__ bets) {
    __shared__ float c2[C], s2[C], cs[C], ss[C];
    int tid = threadIdx.x;
    if (tid < 32) {
        const float invn = 1.f / (float)NN;
        float m2 = g_stat[128 + tid] * invn;
        float v2 = g_stat[160 + tid] * invn - m2*m2;
        float sc2 = __ldg(gam2 + tid) * rsqrtf(v2 + BNE);
        c2[tid] = sc2; s2[tid] = __ldg(bet2 + tid) - m2*sc2;
        float ms = g_stat[64 + tid] * invn;
        float vs = g_stat[96 + tid] * invn - ms*ms;
        float scs = __ldg(gams + tid) * rsqrtf(vs + BNE);
        cs[tid] = scs; ss[tid] = __ldg(bets + tid) - ms*scs;
    }
    __syncthreads();
    int i = blockIdx.x * 256 + tid;
    if (i >= NN*C) return;
    int c = i & 31;
    float v2 = g_y2[i] * c2[c] + s2[c];
    float vs = g_ys[i] * cs[c] + ss[c];
    float h = v2 + vs;
    out[i] = (h > 0.f) ? h : expm1f(h);
}

// ------------------------------------------------------------------------------
extern "C" void kernel_launch(void* const* d_in, const int* in_sizes, int n_in,
                              void* d_out, int out_size) {
    (void)in_sizes; (void)n_in; (void)out_size;
    const float* x     = (const float*)d_in[0];
    const int*   ei    = (const int*)  d_in[1];
    const float* attr  = (const float*)d_in[2];
    const float* g1    = (const float*)d_in[3];
    const float* mu1   = (const float*)d_in[4];
    const float* sg1   = (const float*)d_in[5];
    const float* root1 = (const float*)d_in[6];
    const float* b1    = (const float*)d_in[7];
    const float* gam1  = (const float*)d_in[8];
    const float* bet1  = (const float*)d_in[9];
    const float* g2    = (const float*)d_in[10];
    const float* mu2   = (const float*)d_in[11];
    const float* sg2   = (const float*)d_in[12];
    const float* root2 = (const float*)d_in[13];
    const float* b2    = (const float*)d_in[14];
    const float* gam2  = (const float*)d_in[15];
    const float* bet2  = (const float*)d_in[16];
    const float* gs    = (const float*)d_in[17];
    const float* mus   = (const float*)d_in[18];
    const float* sgs   = (const float*)d_in[19];
    const float* roots = (const float*)d_in[20];
    const float* bs    = (const float*)d_in[21];
    const float* gams  = (const float*)d_in[22];
    const float* bets  = (const float*)d_in[23];
    float* out = (float*)d_out;

    const int nb_scan = (NN + 1023) / 1024;

    k_zg   <<<(NN + 255)/256, 256>>>(mu1, sg1, mu2, sg2, mus, sgs);
    k_count<<<(EE/4 + 255)/256, 256>>>(ei);
    k_scan1<<<nb_scan, 1024>>>();
    k_scan3<<<(NN + 255)/256, 256>>>();
    k_fill <<<(EE + 255)/256, 256>>>(ei, attr);
    k_edge1<<<(NN + 7)/8,     256>>>(x);
    k_postA<<<(NN + 63)/64,   256>>>(x, g1, gs, root1, b1, roots, bs);
    k_prepB<<<(NN*C/4 + 255)/256, 256>>>(gam1, bet1);
    k_edge2<<<(NN + 7)/8,     256>>>();
    k_postB<<<(NN + 63)/64,   256>>>(g2, root2, b2);
    k_final<<<(NN*C + 255)/256, 256>>>(out, gam2, bet2, gams, bets);
}